// round 2
// baseline (speedup 1.0000x reference)
#include <cuda_runtime.h>
#include <cuda_bf16.h>

// Problem shape (fixed per problem instance)
#define B_MAX 16
#define S_DIM 4096
#define D_DIM 512
#define D4 (D_DIM / 4)          // 128 float4 per row
#define NCHUNK 32               // row chunks per batch
#define ROWS_PER_CHUNK (S_DIM / NCHUNK)   // 128
#define THREADS 128             // one float4 column-slot per thread

// Deterministic partial-sum scratch: [B][NCHUNK][D] floats = 1 MiB
__device__ float4 g_scratch[B_MAX * NCHUNK * D4];

// xs_len may be int32 (JAX x64-disabled downcast) or int64.
// Little-endian sniff: word[1] is the high half of len[0] if int64 (== 0,
// since len <= 4096), or len[1] if int32 (in [1,4096], != 0).
// Only touches the first 8 bytes -> in-bounds for either dtype.
__device__ __forceinline__ long long read_len(const void* p, int b)
{
    const int* p32 = (const int*)p;
    if (p32[1] == 0) {
        return ((const long long*)p)[b];   // int64 layout
    } else {
        return (long long)p32[b];          // int32 layout
    }
}

__global__ __launch_bounds__(THREADS)
void mean_accum_kernel(const float* __restrict__ xs,
                       const void* __restrict__ xs_len)
{
    const int chunk = blockIdx.x;        // 0..NCHUNK-1
    const int b     = blockIdx.y;        // 0..B-1
    const int t     = threadIdx.x;       // 0..127 -> float4 column slot

    const long long L = read_len(xs_len, b);
    const int r0 = chunk * ROWS_PER_CHUNK;
    int r1 = r0 + ROWS_PER_CHUNK;
    if ((long long)r1 > L) r1 = (int)L;

    float4* out = &g_scratch[(b * NCHUNK + chunk) * D4 + t];

    if (r0 >= r1) {
        // chunk fully masked out
        *out = make_float4(0.f, 0.f, 0.f, 0.f);
        return;
    }

    const float4* base = reinterpret_cast<const float4*>(
        xs + (size_t)b * S_DIM * D_DIM) + t;

    float4 a0 = make_float4(0.f, 0.f, 0.f, 0.f);
    float4 a1 = make_float4(0.f, 0.f, 0.f, 0.f);
    float4 a2 = make_float4(0.f, 0.f, 0.f, 0.f);
    float4 a3 = make_float4(0.f, 0.f, 0.f, 0.f);

    int r = r0;
    // 4-row unroll: 4 independent float4 loads in flight per iter (MLP>=4)
    for (; r + 4 <= r1; r += 4) {
        float4 v0 = base[(size_t)(r + 0) * D4];
        float4 v1 = base[(size_t)(r + 1) * D4];
        float4 v2 = base[(size_t)(r + 2) * D4];
        float4 v3 = base[(size_t)(r + 3) * D4];
        a0.x += v0.x; a0.y += v0.y; a0.z += v0.z; a0.w += v0.w;
        a1.x += v1.x; a1.y += v1.y; a1.z += v1.z; a1.w += v1.w;
        a2.x += v2.x; a2.y += v2.y; a2.z += v2.z; a2.w += v2.w;
        a3.x += v3.x; a3.y += v3.y; a3.z += v3.z; a3.w += v3.w;
    }
    for (; r < r1; r++) {
        float4 v = base[(size_t)r * D4];
        a0.x += v.x; a0.y += v.y; a0.z += v.z; a0.w += v.w;
    }

    float4 acc;
    acc.x = (a0.x + a1.x) + (a2.x + a3.x);
    acc.y = (a0.y + a1.y) + (a2.y + a3.y);
    acc.z = (a0.z + a1.z) + (a2.z + a3.z);
    acc.w = (a0.w + a1.w) + (a2.w + a3.w);

    *out = acc;
}

__global__ __launch_bounds__(THREADS)
void mean_finish_kernel(const void* __restrict__ xs_len,
                        float* __restrict__ out)
{
    const int b = blockIdx.x;
    const int t = threadIdx.x;

    float4 s = make_float4(0.f, 0.f, 0.f, 0.f);
    const float4* src = &g_scratch[b * NCHUNK * D4 + t];
    #pragma unroll
    for (int c = 0; c < NCHUNK; c++) {
        float4 v = src[c * D4];
        s.x += v.x; s.y += v.y; s.z += v.z; s.w += v.w;
    }

    const float inv = 1.0f / (float)read_len(xs_len, b);
    s.x *= inv; s.y *= inv; s.z *= inv; s.w *= inv;

    reinterpret_cast<float4*>(out + (size_t)b * D_DIM)[t] = s;
}

extern "C" void kernel_launch(void* const* d_in, const int* in_sizes, int n_in,
                              void* d_out, int out_size)
{
    const float* xs     = (const float*)d_in[0];
    const void*  xs_len = d_in[1];
    float*       out    = (float*)d_out;

    const int B = in_sizes[1];   // number of sequences (16)

    dim3 grid1(NCHUNK, B);
    mean_accum_kernel<<<grid1, THREADS>>>(xs, xs_len);
    mean_finish_kernel<<<B, THREADS>>>(xs_len, out);
}